// round 14
// baseline (speedup 1.0000x reference)
#include <cuda_runtime.h>

#define BB 4
#define CC 128
#define CQ 16
#define NN 4096
#define TT 64
#define CH 16
#define NCOMP 640
#define NZERO 1120
#define NVF 256

// ---------------- scratch ----------------
__device__ float g_q[(size_t)BB*NN*CQ];      // [b][n][d]
__device__ float g_k[(size_t)BB*CQ*NN];      // [b][d][n]
__device__ float g_v[(size_t)BB*CC*NN];      // [b][c][n]
__device__ float g_sum[(size_t)BB*NN];       // softmax denominators (atomic)
__device__ uint4 g_vf[(size_t)BB*64*2048];   // V tf32 A-fragments, 32KB per (b,mt)

// ---------------- helpers ----------------
static __device__ __forceinline__ unsigned long long pack2(float x, float y) {
    unsigned long long r;
    asm("mov.b64 %0, {%1, %2};" : "=l"(r) : "f"(x), "f"(y));
    return r;
}
static __device__ __forceinline__ void fma2(unsigned long long& d,
                                            unsigned long long a,
                                            unsigned long long b) {
    asm("fma.rn.f32x2 %0, %1, %2, %3;" : "=l"(d) : "l"(a), "l"(b), "l"(d));
}
static __device__ __forceinline__ float2 unpack2(unsigned long long v) {
    float x, y;
    asm("mov.b64 {%0, %1}, %2;" : "=f"(x), "=f"(y) : "l"(v));
    return make_float2(x, y);
}
static __device__ __forceinline__ unsigned f2tf32(float f) {
    unsigned r;
    asm("cvt.rn.tf32.f32 %0, %1;" : "=r"(r) : "f"(f));
    return r;
}
static __device__ __forceinline__ void mma_tf32(float c[4],
                                                const unsigned a[4],
                                                const unsigned b0, const unsigned b1) {
    asm volatile("mma.sync.aligned.m16n8k8.row.col.f32.tf32.tf32.f32 "
        "{%0,%1,%2,%3}, {%4,%5,%6,%7}, {%8,%9}, {%0,%1,%2,%3};"
        : "+f"(c[0]), "+f"(c[1]), "+f"(c[2]), "+f"(c[3])
        : "r"(a[0]), "r"(a[1]), "r"(a[2]), "r"(a[3]), "r"(b0), "r"(b1));
}
#define CP16(dst, src) \
    asm volatile("cp.async.cg.shared.global [%0], [%1], 16;" \
                 :: "r"(dst), "l"(src) : "memory")
#define CP_COMMIT() asm volatile("cp.async.commit_group;" ::: "memory")
#define CP_WAIT1()  asm volatile("cp.async.wait_group 1;" ::: "memory")
#define CP_WAIT0()  asm volatile("cp.async.wait_group 0;" ::: "memory")

// ================= kernel 1: q,k,v + out-init + g_sum zero =================
__global__ __launch_bounds__(256) void qkv_kernel(
    const float* __restrict__ x,
    const float* __restrict__ wq, const float* __restrict__ bq,
    const float* __restrict__ wk, const float* __restrict__ bk,
    const float* __restrict__ wv, const float* __restrict__ bv,
    float* __restrict__ outp)
{
    extern __shared__ float sm1[];
    float* ws = sm1;                 // [160][132]
    float* bs = ws + 160*132;        // [160]
    float* xs = bs + 160;            // 2 x [128][32]

    int bid = blockIdx.x;
    int b = bid & 3, tb = bid >> 2;
    int n0 = tb * 64;
    int t = threadIdx.x;
    int lane = t & 31;
    int j0 = (t >> 5) * 4;

    if (t < 64) g_sum[(size_t)b*NN + n0 + t] = 0.f;

    unsigned xs_base;
    { unsigned long long g = (unsigned long long)__cvta_generic_to_shared(xs);
      xs_base = (unsigned)g; }
    const float* xsrc = x + (size_t)b*CC*NN + n0;
    {
        #pragma unroll
        for (int q = 0; q < 4; q++) {
            int idx = t + q*256;
            int c = idx >> 3, f4 = (idx & 7) << 2;
            CP16(xs_base + (unsigned)((c*32 + f4) << 2),
                 (const void*)(xsrc + (size_t)c*NN + f4));
        }
        CP_COMMIT();
    }

    #pragma unroll
    for (int i = 0; i < 20; i++) {
        int idx = t + i*256;
        int o = idx >> 5, c4 = (idx & 31) << 2;
        const float* src;
        if (o < CQ)        src = wq + o*CC + c4;
        else if (o < 2*CQ) src = wk + (o-CQ)*CC + c4;
        else               src = wv + (o-2*CQ)*CC + c4;
        *(float4*)(ws + o*132 + c4) = *(const float4*)src;
    }
    if (t < 160) bs[t] = (t < CQ) ? bq[t] : (t < 2*CQ) ? bk[t-CQ] : bv[t-2*CQ];

    // out = x (pre-init for atomic accumulation)
    #pragma unroll
    for (int i = 0; i < 8; i++) {
        int idx = t + i*256;
        int c = idx >> 4, n4 = (idx & 15) << 2;
        size_t a = ((size_t)b*CC + c)*NN + n0 + n4;
        *(float4*)(outp + a) = *(const float4*)(x + a);
    }

    float bias[5];
    #pragma unroll
    for (int g = 0; g < 5; g++) bias[g] = bs[lane + 32*g];

    #pragma unroll
    for (int st = 0; st < 2; st++) {
        if (st == 0) {
            #pragma unroll
            for (int q = 0; q < 4; q++) {
                int idx = t + q*256;
                int c = idx >> 3, f4 = (idx & 7) << 2;
                CP16(xs_base + (unsigned)((4096 + c*32 + f4) << 2),
                     (const void*)(xsrc + (size_t)c*NN + 32 + f4));
            }
            CP_COMMIT();
            CP_WAIT1();
        } else {
            CP_WAIT0();
        }
        __syncthreads();

        const float* xt = xs + st*4096;
        unsigned long long acc2[5][2];
        #pragma unroll
        for (int g = 0; g < 5; g++) { acc2[g][0] = 0ull; acc2[g][1] = 0ull; }

        #pragma unroll 4
        for (int c4 = 0; c4 < 32; c4++) {
            ulonglong2 xp[4];
            #pragma unroll
            for (int cc = 0; cc < 4; cc++)
                xp[cc] = *(const ulonglong2*)(xt + (c4*4 + cc)*32 + j0);
            #pragma unroll
            for (int g = 0; g < 5; g++) {
                float4 w4 = *(const float4*)(ws + (lane + 32*g)*132 + c4*4);
                unsigned long long wp;
                wp = pack2(w4.x, w4.x);
                fma2(acc2[g][0], wp, xp[0].x); fma2(acc2[g][1], wp, xp[0].y);
                wp = pack2(w4.y, w4.y);
                fma2(acc2[g][0], wp, xp[1].x); fma2(acc2[g][1], wp, xp[1].y);
                wp = pack2(w4.z, w4.z);
                fma2(acc2[g][0], wp, xp[2].x); fma2(acc2[g][1], wp, xp[2].y);
                wp = pack2(w4.w, w4.w);
                fma2(acc2[g][0], wp, xp[3].x); fma2(acc2[g][1], wp, xp[3].y);
            }
        }

        int nb = n0 + st*32 + j0;
        #pragma unroll
        for (int g = 0; g < 5; g++) {
            int o = lane + 32*g;
            float2 u0 = unpack2(acc2[g][0]);
            float2 u1 = unpack2(acc2[g][1]);
            float v0 = u0.x + bias[g], v1 = u0.y + bias[g];
            float v2 = u1.x + bias[g], v3 = u1.y + bias[g];
            if (o < CQ) {
                g_q[((size_t)b*NN + nb)*CQ + o]     = v0;
                g_q[((size_t)b*NN + nb + 1)*CQ + o] = v1;
                g_q[((size_t)b*NN + nb + 2)*CQ + o] = v2;
                g_q[((size_t)b*NN + nb + 3)*CQ + o] = v3;
            } else {
                float* row = (o < 2*CQ) ? (g_k + ((size_t)b*CQ + (o-CQ))*NN)
                                        : (g_v + ((size_t)b*CC + (o-2*CQ))*NN);
                *(float4*)(row + nb) = make_float4(v0, v1, v2, v3);
            }
        }
    }
}

// ================= kernel 2: chunked sum-exp (2-row phase A) + V-frag build =
__global__ __launch_bounds__(256) void sumexp_kernel() {
    __shared__ float ksm[2*CQ*TT];
    int bid = blockIdx.x;
    int t = threadIdx.x;

    if (bid >= NCOMP) {                      // ---- V fragment build role ----
        int vb = bid - NCOMP;                // vb = b*64 + mt
        int b = vb >> 6;
        int mt = vb & 63;
        int ksv = t >> 5, lane = t & 31;
        int m = mt*64 + ksv*8 + (lane & 3);
        int cb = lane >> 2;
        const float* vp = g_v + (size_t)b*CC*NN;
        #pragma unroll
        for (int wc = 0; wc < 8; wc++) {
            int c = wc*16 + cb;
            uint4 u;
            u.x = f2tf32(vp[(size_t)c*NN + m]);
            u.y = f2tf32(vp[(size_t)(c+8)*NN + m]);
            u.z = f2tf32(vp[(size_t)c*NN + m + 4]);
            u.w = f2tf32(vp[(size_t)(c+8)*NN + m + 4]);
            g_vf[(size_t)vb*2048 + (wc*8 + ksv)*32 + lane] = u;
        }
        return;
    }

    int b = bid / 160, rem = bid % 160;
    int r = 0;
    for (; r < 64; r++) { int nc = 1 + (r>>4); if (rem < nc) break; rem -= nc; }
    int n0 = r*TT;
    int ct0 = rem*CH;
    int nct = min(CH, r + 1 - ct0);
    int pi2 = t >> 3, pj0 = (t & 7) << 3;    // rows (pi2, pi2+32), 8 cols
    int sd = t >> 4, sj4 = (t & 15) << 2;

    float qlo[CQ], qhi[CQ];
    const float* qpl = g_q + ((size_t)b*NN + n0 + pi2)*CQ;
    const float* qph = qpl + 32*CQ;
    #pragma unroll
    for (int d = 0; d < CQ; d += 4) {
        float4 a = *(const float4*)(qpl + d);
        qlo[d] = a.x; qlo[d+1] = a.y; qlo[d+2] = a.z; qlo[d+3] = a.w;
        float4 h = *(const float4*)(qph + d);
        qhi[d] = h.x; qhi[d+1] = h.y; qhi[d+2] = h.z; qhi[d+3] = h.w;
    }
    const float* krow = g_k + ((size_t)b*CQ + sd)*NN + sj4;

    // prestage tile 0
    *(float4*)(ksm + sd*TT + sj4) = *(const float4*)(krow + ct0*TT);

    float slo = 0.f, shi = 0.f;
    for (int tt = 0; tt < nct; tt++) {
        int m0 = (ct0 + tt)*TT;
        __syncthreads();
        bool have = (tt + 1 < nct);
        float4 kreg;
        if (have) kreg = *(const float4*)(krow + m0 + TT);
        const float* ks = ksm + (tt & 1)*1024;

        unsigned long long elo[4], ehi[4];
        #pragma unroll
        for (int p = 0; p < 4; p++) { elo[p] = 0ull; ehi[p] = 0ull; }
        #pragma unroll
        for (int d = 0; d < CQ; d++) {
            const ulonglong2* kp = (const ulonglong2*)(ks + d*TT + pj0);
            ulonglong2 kA = kp[0], kB = kp[1];
            unsigned long long qdl = pack2(qlo[d], qlo[d]);
            unsigned long long qdh = pack2(qhi[d], qhi[d]);
            fma2(elo[0], qdl, kA.x); fma2(elo[1], qdl, kA.y);
            fma2(elo[2], qdl, kB.x); fma2(elo[3], qdl, kB.y);
            fma2(ehi[0], qdh, kA.x); fma2(ehi[1], qdh, kA.y);
            fma2(ehi[2], qdh, kB.x); fma2(ehi[3], qdh, kB.y);
        }
        #pragma unroll
        for (int p = 0; p < 4; p++) {
            float2 ul = unpack2(elo[p]);
            slo += __expf(ul.x) + __expf(ul.y);
            float2 uh = unpack2(ehi[p]);
            shi += __expf(uh.x) + __expf(uh.y);
        }
        if (have)
            *(float4*)(ksm + ((tt+1) & 1)*1024 + sd*TT + sj4) = kreg;
    }
    #pragma unroll
    for (int off = 1; off <= 4; off <<= 1) {
        slo += __shfl_xor_sync(0xffffffffu, slo, off);
        shi += __shfl_xor_sync(0xffffffffu, shi, off);
    }
    if ((t & 7) == 0) {
        atomicAdd(g_sum + (size_t)b*NN + n0 + pi2,      slo);
        atomicAdd(g_sum + (size_t)b*NN + n0 + pi2 + 32, shi);
    }
}

// ================= kernel 3: pipelined attention + HMMA tf32 PV =============
// smem floats: K 2x1024 @0, bf 2x4096 @2048, vf 2x8192 @10240  (104KB)
// V(tt) copy issued at iteration tt (after the barrier), consumed by
// phase B(tt) during iteration tt+1 — writer/reader of each V buffer are
// always separated by the CP_WAIT0+barrier at the top of the iteration.
__global__ __launch_bounds__(256, 2) void attn_kernel(
    const float* __restrict__ gamma,
    float* __restrict__ outp, float* __restrict__ attnp)
{
    extern __shared__ float smf[];
    float* bf = smf + 2048;
    float* vf = smf + 10240;

    int bid = blockIdx.x;
    int t = threadIdx.x;

    if (bid >= NCOMP) {                       // ---- zero role ----
        int zi = bid - NCOMP;
        int b = zi / 280, rem = zi % 280;
        int ct = 1;
        for (; ct < 64; ct++) { int np = (ct + 7) >> 3; if (rem < np) break; rem -= np; }
        int r0 = rem * 512;
        int rend = min(r0 + 512, ct * 64);
        float4 z = make_float4(0.f, 0.f, 0.f, 0.f);
        size_t colo = (size_t)ct*64 + (size_t)(t & 15)*4;
        for (int row = r0 + (t >> 4); row < rend; row += 16)
            *(float4*)(attnp + ((size_t)b*NN + row)*NN + colo) = z;
        return;
    }

    int b = bid / 160, rem = bid % 160;
    int r = 0;
    for (; r < 64; r++) { int nc = 1 + (r>>4); if (rem < nc) break; rem -= nc; }
    int n0 = r*TT;
    int ct0 = rem*CH;
    int nct = min(CH, r + 1 - ct0);

    int lane = t & 31, w = t >> 5;
    int pi2 = t >> 3, pj0 = (t & 7) << 3;    // rows (pi2, pi2+32), 8 cols
    int ksv = t & 7;                          // this thread owns m-group ksv
    int sd = t >> 4, sj4 = (t & 15) << 2;

    unsigned vf_base;
    { unsigned long long g = (unsigned long long)__cvta_generic_to_shared(vf);
      vf_base = (unsigned)g; }

    float qlo[CQ], qhi[CQ];
    const float* qpl = g_q + ((size_t)b*NN + n0 + pi2)*CQ;
    const float* qph = qpl + 32*CQ;
    #pragma unroll
    for (int d = 0; d < CQ; d += 4) {
        float4 a = *(const float4*)(qpl + d);
        qlo[d] = a.x; qlo[d+1] = a.y; qlo[d+2] = a.z; qlo[d+3] = a.w;
        float4 h = *(const float4*)(qph + d);
        qhi[d] = h.x; qhi[d+1] = h.y; qhi[d+2] = h.z; qhi[d+3] = h.w;
    }
    float rinv_lo = 1.0f / g_sum[(size_t)b*NN + n0 + pi2];
    float rinv_hi = 1.0f / g_sum[(size_t)b*NN + n0 + pi2 + 32];
    float* arow_lo = attnp + ((size_t)b*NN + n0 + pi2)*NN;
    float* arow_hi = arow_lo + (size_t)32*NN;
    const float* krow = g_k + ((size_t)b*CQ + sd)*NN + sj4;
    const uint4* vtile0 = g_vf + (size_t)(b*64 + ct0)*2048;

    float cacc[8][4];
    #pragma unroll
    for (int nb = 0; nb < 8; nb++)
        #pragma unroll
        for (int q = 0; q < 4; q++) cacc[nb][q] = 0.f;

    int lsb_lo = (pi2 & 7) << 2, nbp_lo = pi2 >> 4, nblo_lo = (pi2 >> 3) & 1;
    int rh = pi2 + 32;
    int lsb_hi = (rh & 7) << 2,  nbp_hi = rh >> 4,  nblo_hi = (rh >> 3) & 1;

    // prestage K tile 0 (V copies are issued inside the loop)
    *(float4*)(smf + sd*TT + sj4) = *(const float4*)(krow + ct0*TT);

    for (int tt = 0; tt < nct; tt++) {
        int m0 = (ct0 + tt)*TT;
        bool have = (tt + 1 < nct);
        CP_WAIT0();                           // V(tt-1) fully landed
        __syncthreads();                      // publishes V(tt-1), bf(tt-1), K(tt)

        // issue V(tt) copy into buffer tt&1 (read next iteration by phase B(tt))
        {
            const uint4* src = vtile0 + (size_t)tt*2048 + t;
            unsigned dst = vf_base + (unsigned)((tt & 1)*32768 + (t << 4));
            #pragma unroll
            for (int q = 0; q < 8; q++)
                CP16(dst + q*4096, (const void*)(src + q*256));
            CP_COMMIT();
        }
        float4 kreg;
        if (have) kreg = *(const float4*)(krow + m0 + TT);
        const float* ks = smf + (tt & 1)*1024;
        float* bft = bf + (tt & 1)*4096;

        // ---- phase A(tt): energy (2 rows x 8 cols) -> p; STG; B frags ----
        unsigned long long elo[4], ehi[4];
        #pragma unroll
        for (int p = 0; p < 4; p++) { elo[p] = 0ull; ehi[p] = 0ull; }
        #pragma unroll
        for (int d = 0; d < CQ; d++) {
            const ulonglong2* kp = (const ulonglong2*)(ks + d*TT + pj0);
            ulonglong2 kA = kp[0], kB = kp[1];
            unsigned long long qdl = pack2(qlo[d], qlo[d]);
            unsigned long long qdh = pack2(qhi[d], qhi[d]);
            fma2(elo[0], qdl, kA.x); fma2(elo[1], qdl, kA.y);
            fma2(elo[2], qdl, kB.x); fma2(elo[3], qdl, kB.y);
            fma2(ehi[0], qdh, kA.x); fma2(ehi[1], qdh, kA.y);
            fma2(ehi[2], qdh, kB.x); fma2(ehi[3], qdh, kB.y);
        }
        float pvl[8], pvh[8];
        #pragma unroll
        for (int p = 0; p < 4; p++) {
            float2 ul = unpack2(elo[p]);
            pvl[2*p]   = __expf(ul.x)*rinv_lo;
            pvl[2*p+1] = __expf(ul.y)*rinv_lo;
            float2 uh = unpack2(ehi[p]);
            pvh[2*p]   = __expf(uh.x)*rinv_hi;
            pvh[2*p+1] = __expf(uh.y)*rinv_hi;
        }
        *(float4*)(arow_lo + m0 + pj0)     = make_float4(pvl[0], pvl[1], pvl[2], pvl[3]);
        *(float4*)(arow_lo + m0 + pj0 + 4) = make_float4(pvl[4], pvl[5], pvl[6], pvl[7]);
        *(float4*)(arow_hi + m0 + pj0)     = make_float4(pvh[0], pvh[1], pvh[2], pvh[3]);
        *(float4*)(arow_hi + m0 + pj0 + 4) = make_float4(pvh[4], pvh[5], pvh[6], pvh[7]);
        #pragma unroll
        for (int j = 0; j < 4; j++) {
            int ls = lsb_lo + j;
            int s = (nbp_lo + (ls >> 1) + ksv) & 3;
            uint2 u2;
            u2.x = f2tf32(pvl[j]);
            u2.y = f2tf32(pvl[j + 4]);
            *(uint2*)(bft + ksv*512 + ls*16 + s*4 + nblo_lo*2) = u2;
        }
        #pragma unroll
        for (int j = 0; j < 4; j++) {
            int ls = lsb_hi + j;
            int s = (nbp_hi + (ls >> 1) + ksv) & 3;
            uint2 u2;
            u2.x = f2tf32(pvh[j]);
            u2.y = f2tf32(pvh[j + 4]);
            *(uint2*)(bft + ksv*512 + ls*16 + s*4 + nblo_hi*2) = u2;
        }
        if (have)
            *(float4*)(smf + ((tt+1) & 1)*1024 + sd*TT + sj4) = kreg;

        // ---- phase B(tt-1): MMA on previous tile (no barrier in between) ----
        if (tt > 0) {
            int pb = (tt - 1) & 1;
            const uint4* vsp = (const uint4*)(vf + pb*8192) + w*8*32 + lane;
            const float* bfp = bf + pb*4096;
            #pragma unroll
            for (int kv = 0; kv < 8; kv++) {
                uint4 a = vsp[kv*32];
                unsigned ar[4] = {a.x, a.y, a.z, a.w};
                #pragma unroll
                for (int np2 = 0; np2 < 4; np2++) {
                    int s = (np2 + (lane >> 1) + kv) & 3;
                    uint4 bv = *(const uint4*)(bfp + kv*512 + lane*16 + s*4);
                    mma_tf32(cacc[2*np2],     ar, bv.x, bv.y);
                    mma_tf32(cacc[2*np2 + 1], ar, bv.z, bv.w);
                }
            }
        }
    }

    // ---- drain: final phase B(nct-1) ----
    CP_WAIT0();
    __syncthreads();
    {
        int pb = (nct - 1) & 1;
        const uint4* vsp = (const uint4*)(vf + pb*8192) + w*8*32 + lane;
        const float* bfp = bf + pb*4096;
        #pragma unroll
        for (int kv = 0; kv < 8; kv++) {
            uint4 a = vsp[kv*32];
            unsigned ar[4] = {a.x, a.y, a.z, a.w};
            #pragma unroll
            for (int np2 = 0; np2 < 4; np2++) {
                int s = (np2 + (lane >> 1) + kv) & 3;
                uint4 bv = *(const uint4*)(bfp + kv*512 + lane*16 + s*4);
                mma_tf32(cacc[2*np2],     ar, bv.x, bv.y);
                mma_tf32(cacc[2*np2 + 1], ar, bv.z, bv.w);
            }
        }
    }

    // ---- epilogue: atomic out accumulation ----
    float gm = gamma[0];
    int rowc = lane >> 2, colb = (lane & 3) << 1;
    #pragma unroll
    for (int nb = 0; nb < 8; nb++) {
        int i = nb*8 + colb;
        size_t a0 = ((size_t)b*CC + w*16 + rowc)*NN + n0 + i;
        atomicAdd(outp + a0,            gm*cacc[nb][0]);
        atomicAdd(outp + a0 + 1,        gm*cacc[nb][1]);
        atomicAdd(outp + a0 + 8*NN,     gm*cacc[nb][2]);
        atomicAdd(outp + a0 + 8*NN + 1, gm*cacc[nb][3]);
    }
}

// ================= launch =================
extern "C" void kernel_launch(void* const* d_in, const int* in_sizes, int n_in,
                              void* d_out, int out_size)
{
    const float* x     = (const float*)d_in[0];
    const float* wq    = (const float*)d_in[1];
    const float* bq    = (const float*)d_in[2];
    const float* wk    = (const float*)d_in[3];
    const float* bk    = (const float*)d_in[4];
    const float* wv    = (const float*)d_in[5];
    const float* bv    = (const float*)d_in[6];
    const float* gamma = (const float*)d_in[7];

    float* outp  = (float*)d_out;
    float* attnp = outp + (size_t)BB*CC*NN;

    const int SM1 = (160*132 + 160 + 2*4096) * 4;      // 117,888 B
    const int SM3 = (2048 + 2*4096 + 2*8192) * 4;      // 106,496 B
    cudaFuncSetAttribute(qkv_kernel,  cudaFuncAttributeMaxDynamicSharedMemorySize, SM1);
    cudaFuncSetAttribute(attn_kernel, cudaFuncAttributeMaxDynamicSharedMemorySize, SM3);

    qkv_kernel<<<BB*(NN/64), 256, SM1>>>(x, wq, bq, wk, bk, wv, bv, outp);
    sumexp_kernel<<<NCOMP + NVF, 256>>>();
    attn_kernel<<<NCOMP + NZERO, 256, SM3>>>(gamma, outp, attnp);
}

// round 15
// speedup vs baseline: 1.0983x; 1.0983x over previous
#include <cuda_runtime.h>

#define BB 4
#define CC 128
#define CQ 16
#define NN 4096
#define TT 64
#define CH 16
#define NCOMP 640
#define NZERO 1120
#define NVF 256

// ---------------- scratch ----------------
__device__ float g_q[(size_t)BB*NN*CQ];      // [b][n][d]
__device__ float g_k[(size_t)BB*CQ*NN];      // [b][d][n]
__device__ float g_v[(size_t)BB*CC*NN];      // [b][c][n]
__device__ float g_sum[(size_t)BB*NN];       // softmax denominators (atomic)
__device__ uint4 g_vf[(size_t)BB*64*2048];   // V tf32 A-fragments, 32KB per (b,mt)

// ---------------- helpers ----------------
static __device__ __forceinline__ unsigned long long pack2(float x, float y) {
    unsigned long long r;
    asm("mov.b64 %0, {%1, %2};" : "=l"(r) : "f"(x), "f"(y));
    return r;
}
static __device__ __forceinline__ void fma2(unsigned long long& d,
                                            unsigned long long a,
                                            unsigned long long b) {
    asm("fma.rn.f32x2 %0, %1, %2, %3;" : "=l"(d) : "l"(a), "l"(b), "l"(d));
}
static __device__ __forceinline__ float2 unpack2(unsigned long long v) {
    float x, y;
    asm("mov.b64 {%0, %1}, %2;" : "=f"(x), "=f"(y) : "l"(v));
    return make_float2(x, y);
}
static __device__ __forceinline__ unsigned f2tf32(float f) {
    unsigned r;
    asm("cvt.rn.tf32.f32 %0, %1;" : "=r"(r) : "f"(f));
    return r;
}
static __device__ __forceinline__ void mma_tf32(float c[4],
                                                const unsigned a[4],
                                                const unsigned b0, const unsigned b1) {
    asm volatile("mma.sync.aligned.m16n8k8.row.col.f32.tf32.tf32.f32 "
        "{%0,%1,%2,%3}, {%4,%5,%6,%7}, {%8,%9}, {%0,%1,%2,%3};"
        : "+f"(c[0]), "+f"(c[1]), "+f"(c[2]), "+f"(c[3])
        : "r"(a[0]), "r"(a[1]), "r"(a[2]), "r"(a[3]), "r"(b0), "r"(b1));
}
#define CP16(dst, src) \
    asm volatile("cp.async.cg.shared.global [%0], [%1], 16;" \
                 :: "r"(dst), "l"(src) : "memory")
#define CP_COMMIT() asm volatile("cp.async.commit_group;" ::: "memory")
#define CP_WAIT1()  asm volatile("cp.async.wait_group 1;" ::: "memory")
#define CP_WAIT0()  asm volatile("cp.async.wait_group 0;" ::: "memory")

// ================= kernel 1: q,k,v + out-init + g_sum zero =================
__global__ __launch_bounds__(256) void qkv_kernel(
    const float* __restrict__ x,
    const float* __restrict__ wq, const float* __restrict__ bq,
    const float* __restrict__ wk, const float* __restrict__ bk,
    const float* __restrict__ wv, const float* __restrict__ bv,
    float* __restrict__ outp)
{
    extern __shared__ float sm1[];
    float* ws = sm1;                 // [160][132]
    float* bs = ws + 160*132;        // [160]
    float* xs = bs + 160;            // 2 x [128][32]

    int bid = blockIdx.x;
    int b = bid & 3, tb = bid >> 2;
    int n0 = tb * 64;
    int t = threadIdx.x;
    int lane = t & 31;
    int j0 = (t >> 5) * 4;

    if (t < 64) g_sum[(size_t)b*NN + n0 + t] = 0.f;

    unsigned xs_base;
    { unsigned long long g = (unsigned long long)__cvta_generic_to_shared(xs);
      xs_base = (unsigned)g; }
    const float* xsrc = x + (size_t)b*CC*NN + n0;
    {
        #pragma unroll
        for (int q = 0; q < 4; q++) {
            int idx = t + q*256;
            int c = idx >> 3, f4 = (idx & 7) << 2;
            CP16(xs_base + (unsigned)((c*32 + f4) << 2),
                 (const void*)(xsrc + (size_t)c*NN + f4));
        }
        CP_COMMIT();
    }

    #pragma unroll
    for (int i = 0; i < 20; i++) {
        int idx = t + i*256;
        int o = idx >> 5, c4 = (idx & 31) << 2;
        const float* src;
        if (o < CQ)        src = wq + o*CC + c4;
        else if (o < 2*CQ) src = wk + (o-CQ)*CC + c4;
        else               src = wv + (o-2*CQ)*CC + c4;
        *(float4*)(ws + o*132 + c4) = *(const float4*)src;
    }
    if (t < 160) bs[t] = (t < CQ) ? bq[t] : (t < 2*CQ) ? bk[t-CQ] : bv[t-2*CQ];

    // out = x (pre-init for atomic accumulation)
    #pragma unroll
    for (int i = 0; i < 8; i++) {
        int idx = t + i*256;
        int c = idx >> 4, n4 = (idx & 15) << 2;
        size_t a = ((size_t)b*CC + c)*NN + n0 + n4;
        *(float4*)(outp + a) = *(const float4*)(x + a);
    }

    float bias[5];
    #pragma unroll
    for (int g = 0; g < 5; g++) bias[g] = bs[lane + 32*g];

    #pragma unroll
    for (int st = 0; st < 2; st++) {
        if (st == 0) {
            #pragma unroll
            for (int q = 0; q < 4; q++) {
                int idx = t + q*256;
                int c = idx >> 3, f4 = (idx & 7) << 2;
                CP16(xs_base + (unsigned)((4096 + c*32 + f4) << 2),
                     (const void*)(xsrc + (size_t)c*NN + 32 + f4));
            }
            CP_COMMIT();
            CP_WAIT1();
        } else {
            CP_WAIT0();
        }
        __syncthreads();

        const float* xt = xs + st*4096;
        unsigned long long acc2[5][2];
        #pragma unroll
        for (int g = 0; g < 5; g++) { acc2[g][0] = 0ull; acc2[g][1] = 0ull; }

        #pragma unroll 4
        for (int c4 = 0; c4 < 32; c4++) {
            ulonglong2 xp[4];
            #pragma unroll
            for (int cc = 0; cc < 4; cc++)
                xp[cc] = *(const ulonglong2*)(xt + (c4*4 + cc)*32 + j0);
            #pragma unroll
            for (int g = 0; g < 5; g++) {
                float4 w4 = *(const float4*)(ws + (lane + 32*g)*132 + c4*4);
                unsigned long long wp;
                wp = pack2(w4.x, w4.x);
                fma2(acc2[g][0], wp, xp[0].x); fma2(acc2[g][1], wp, xp[0].y);
                wp = pack2(w4.y, w4.y);
                fma2(acc2[g][0], wp, xp[1].x); fma2(acc2[g][1], wp, xp[1].y);
                wp = pack2(w4.z, w4.z);
                fma2(acc2[g][0], wp, xp[2].x); fma2(acc2[g][1], wp, xp[2].y);
                wp = pack2(w4.w, w4.w);
                fma2(acc2[g][0], wp, xp[3].x); fma2(acc2[g][1], wp, xp[3].y);
            }
        }

        int nb = n0 + st*32 + j0;
        #pragma unroll
        for (int g = 0; g < 5; g++) {
            int o = lane + 32*g;
            float2 u0 = unpack2(acc2[g][0]);
            float2 u1 = unpack2(acc2[g][1]);
            float v0 = u0.x + bias[g], v1 = u0.y + bias[g];
            float v2 = u1.x + bias[g], v3 = u1.y + bias[g];
            if (o < CQ) {
                g_q[((size_t)b*NN + nb)*CQ + o]     = v0;
                g_q[((size_t)b*NN + nb + 1)*CQ + o] = v1;
                g_q[((size_t)b*NN + nb + 2)*CQ + o] = v2;
                g_q[((size_t)b*NN + nb + 3)*CQ + o] = v3;
            } else {
                float* row = (o < 2*CQ) ? (g_k + ((size_t)b*CQ + (o-CQ))*NN)
                                        : (g_v + ((size_t)b*CC + (o-2*CQ))*NN);
                *(float4*)(row + nb) = make_float4(v0, v1, v2, v3);
            }
        }
    }
}

// ================= kernel 2: energy + UNNORMALIZED exp write + sums =========
// Same energy arithmetic as R12 sumexp; additionally stores exp(e) to attnp.
__global__ __launch_bounds__(256) void expwrite_kernel(float* __restrict__ attnp) {
    __shared__ float ksm[2*CQ*TT];
    int bid = blockIdx.x;
    int t = threadIdx.x;

    if (bid >= NCOMP) {                      // ---- V fragment build role ----
        int vb = bid - NCOMP;                // vb = b*64 + mt
        int b = vb >> 6;
        int mt = vb & 63;
        int ksv = t >> 5, lane = t & 31;
        int m = mt*64 + ksv*8 + (lane & 3);
        int cb = lane >> 2;
        const float* vp = g_v + (size_t)b*CC*NN;
        #pragma unroll
        for (int wc = 0; wc < 8; wc++) {
            int c = wc*16 + cb;
            uint4 u;
            u.x = f2tf32(vp[(size_t)c*NN + m]);
            u.y = f2tf32(vp[(size_t)(c+8)*NN + m]);
            u.z = f2tf32(vp[(size_t)c*NN + m + 4]);
            u.w = f2tf32(vp[(size_t)(c+8)*NN + m + 4]);
            g_vf[(size_t)vb*2048 + (wc*8 + ksv)*32 + lane] = u;
        }
        return;
    }

    int b = bid / 160, rem = bid % 160;
    int r = 0;
    for (; r < 64; r++) { int nc = 1 + (r>>4); if (rem < nc) break; rem -= nc; }
    int n0 = r*TT;
    int ct0 = rem*CH;
    int nct = min(CH, r + 1 - ct0);
    int pi2 = t >> 3, pj0 = (t & 7) << 3;    // rows (pi2, pi2+32), 8 cols
    int sd = t >> 4, sj4 = (t & 15) << 2;

    float qlo[CQ], qhi[CQ];
    const float* qpl = g_q + ((size_t)b*NN + n0 + pi2)*CQ;
    const float* qph = qpl + 32*CQ;
    #pragma unroll
    for (int d = 0; d < CQ; d += 4) {
        float4 a = *(const float4*)(qpl + d);
        qlo[d] = a.x; qlo[d+1] = a.y; qlo[d+2] = a.z; qlo[d+3] = a.w;
        float4 h = *(const float4*)(qph + d);
        qhi[d] = h.x; qhi[d+1] = h.y; qhi[d+2] = h.z; qhi[d+3] = h.w;
    }
    const float* krow = g_k + ((size_t)b*CQ + sd)*NN + sj4;
    float* arow_lo = attnp + ((size_t)b*NN + n0 + pi2)*NN;
    float* arow_hi = arow_lo + (size_t)32*NN;

    // prestage tile 0
    *(float4*)(ksm + sd*TT + sj4) = *(const float4*)(krow + ct0*TT);

    float slo = 0.f, shi = 0.f;
    for (int tt = 0; tt < nct; tt++) {
        int m0 = (ct0 + tt)*TT;
        __syncthreads();
        bool have = (tt + 1 < nct);
        float4 kreg;
        if (have) kreg = *(const float4*)(krow + m0 + TT);
        const float* ks = ksm + (tt & 1)*1024;

        unsigned long long elo[4], ehi[4];
        #pragma unroll
        for (int p = 0; p < 4; p++) { elo[p] = 0ull; ehi[p] = 0ull; }
        #pragma unroll
        for (int d = 0; d < CQ; d++) {
            const ulonglong2* kp = (const ulonglong2*)(ks + d*TT + pj0);
            ulonglong2 kA = kp[0], kB = kp[1];
            unsigned long long qdl = pack2(qlo[d], qlo[d]);
            unsigned long long qdh = pack2(qhi[d], qhi[d]);
            fma2(elo[0], qdl, kA.x); fma2(elo[1], qdl, kA.y);
            fma2(elo[2], qdl, kB.x); fma2(elo[3], qdl, kB.y);
            fma2(ehi[0], qdh, kA.x); fma2(ehi[1], qdh, kA.y);
            fma2(ehi[2], qdh, kB.x); fma2(ehi[3], qdh, kB.y);
        }
        float pvl[8], pvh[8];
        #pragma unroll
        for (int p = 0; p < 4; p++) {
            float2 ul = unpack2(elo[p]);
            pvl[2*p]   = __expf(ul.x);
            pvl[2*p+1] = __expf(ul.y);
            float2 uh = unpack2(ehi[p]);
            pvh[2*p]   = __expf(uh.x);
            pvh[2*p+1] = __expf(uh.y);
        }
        #pragma unroll
        for (int j = 0; j < 8; j++) { slo += pvl[j]; shi += pvh[j]; }
        *(float4*)(arow_lo + m0 + pj0)     = make_float4(pvl[0], pvl[1], pvl[2], pvl[3]);
        *(float4*)(arow_lo + m0 + pj0 + 4) = make_float4(pvl[4], pvl[5], pvl[6], pvl[7]);
        *(float4*)(arow_hi + m0 + pj0)     = make_float4(pvh[0], pvh[1], pvh[2], pvh[3]);
        *(float4*)(arow_hi + m0 + pj0 + 4) = make_float4(pvh[4], pvh[5], pvh[6], pvh[7]);
        if (have)
            *(float4*)(ksm + ((tt+1) & 1)*1024 + sd*TT + sj4) = kreg;
    }
    #pragma unroll
    for (int off = 1; off <= 4; off <<= 1) {
        slo += __shfl_xor_sync(0xffffffffu, slo, off);
        shi += __shfl_xor_sync(0xffffffffu, shi, off);
    }
    if ((t & 7) == 0) {
        atomicAdd(g_sum + (size_t)b*NN + n0 + pi2,      slo);
        atomicAdd(g_sum + (size_t)b*NN + n0 + pi2 + 32, shi);
    }
}

// ================= kernel 3: normalize attnp + HMMA tf32 PV (+zero blocks) ==
// smem floats: bf [4096] @0, ef 2x[4128] @4096 (8 col-panels, stride 516),
//              vf 2x[8192] @12352.  Total 28736 floats = 114,944 B.
__global__ __launch_bounds__(256, 2) void attn_kernel(
    const float* __restrict__ gamma,
    float* __restrict__ outp, float* __restrict__ attnp)
{
    extern __shared__ float smf[];
    float* bf = smf;

    int bid = blockIdx.x;
    int t = threadIdx.x;

    if (bid >= NCOMP) {                       // ---- zero role ----
        int zi = bid - NCOMP;
        int b = zi / 280, rem = zi % 280;
        int ct = 1;
        for (; ct < 64; ct++) { int np = (ct + 7) >> 3; if (rem < np) break; rem -= np; }
        int r0 = rem * 512;
        int rend = min(r0 + 512, ct * 64);
        float4 z = make_float4(0.f, 0.f, 0.f, 0.f);
        size_t colo = (size_t)ct*64 + (size_t)(t & 15)*4;
        for (int row = r0 + (t >> 4); row < rend; row += 16)
            *(float4*)(attnp + ((size_t)b*NN + row)*NN + colo) = z;
        return;
    }

    int b = bid / 160, rem = bid % 160;
    int r = 0;
    for (; r < 64; r++) { int nc = 1 + (r>>4); if (rem < nc) break; rem -= nc; }
    int n0 = r*TT;
    int ct0 = rem*CH;
    int nct = min(CH, r + 1 - ct0);

    int lane = t & 31, w = t >> 5;
    int pi2 = t >> 3;                         // rows (pi2, pi2+32)
    int ksv = t & 7;                          // owns col panel / m-group ksv
    int pj0 = ksv << 3;

    unsigned smem_base;
    { unsigned long long g = (unsigned long long)__cvta_generic_to_shared(smf);
      smem_base = (unsigned)g; }
    unsigned ef_byte0 = smem_base + 4096u*4u;
    unsigned vf_byte0 = smem_base + 12352u*4u;

    float rinv_lo = 1.0f / g_sum[(size_t)b*NN + n0 + pi2];
    float rinv_hi = 1.0f / g_sum[(size_t)b*NN + n0 + pi2 + 32];
    float* arow_lo = attnp + ((size_t)b*NN + n0 + pi2)*NN;
    float* arow_hi = arow_lo + (size_t)32*NN;
    const float* eb0 = attnp + ((size_t)b*NN + n0)*NN;   // exp rows base
    const uint4* vtile0 = g_vf + (size_t)(b*64 + ct0)*2048;

    float cacc[8][4];
    #pragma unroll
    for (int nb = 0; nb < 8; nb++)
        #pragma unroll
        for (int q = 0; q < 4; q++) cacc[nb][q] = 0.f;

    int lsb_lo = (pi2 & 7) << 2, nbp_lo = pi2 >> 4, nblo_lo = (pi2 >> 3) & 1;
    int rh = pi2 + 32;
    int lsb_hi = (rh & 7) << 2,  nbp_hi = rh >> 4,  nblo_hi = (rh >> 3) & 1;

    // per-thread ef copy constants (4 CP16: rows idx>>4, panels sub>>1)
    int erow[4], ep2[4], ehf[4];
    #pragma unroll
    for (int q = 0; q < 4; q++) {
        int idx = t + q*256;
        erow[q] = idx >> 4;
        ep2[q] = (idx & 15) >> 1;
        ehf[q] = idx & 1;
    }

    // pre-loop: issue vf(0) + ef(0)
    {
        const uint4* src = vtile0 + t;
        unsigned dst = vf_byte0 + (unsigned)(t << 4);
        #pragma unroll
        for (int q = 0; q < 8; q++)
            CP16(dst + q*4096, (const void*)(src + q*256));
        int m0 = ct0*TT;
        #pragma unroll
        for (int q = 0; q < 4; q++) {
            const float* esrc = eb0 + (size_t)erow[q]*NN + m0 + ep2[q]*8 + ehf[q]*4;
            unsigned edst = ef_byte0 + (unsigned)((ep2[q]*516 + erow[q]*8 + ehf[q]*4) << 2);
            CP16(edst, (const void*)esrc);
        }
        CP_COMMIT();
    }

    for (int tt = 0; tt < nct; tt++) {
        int m0 = (ct0 + tt)*TT;
        bool have = (tt + 1 < nct);
        CP_WAIT0();                           // vf(tt)+ef(tt) landed (this thread)
        __syncthreads();                      // all visible; bf free

        if (have) {                           // prefetch tile tt+1
            int nb1 = (tt + 1) & 1;
            const uint4* src = vtile0 + (size_t)(tt + 1)*2048 + t;
            unsigned dst = vf_byte0 + (unsigned)(nb1*32768 + (t << 4));
            #pragma unroll
            for (int q = 0; q < 8; q++)
                CP16(dst + q*4096, (const void*)(src + q*256));
            int m1 = m0 + TT;
            #pragma unroll
            for (int q = 0; q < 4; q++) {
                const float* esrc = eb0 + (size_t)erow[q]*NN + m1 + ep2[q]*8 + ehf[q]*4;
                unsigned edst = ef_byte0 + (unsigned)(nb1*16512
                                 + ((ep2[q]*516 + erow[q]*8 + ehf[q]*4) << 2));
                CP16(edst, (const void*)esrc);
            }
            CP_COMMIT();
        }

        // ---- phase A: read exp from smem, normalize, STG, B frags ----
        const float* efb = smf + 4096 + (tt & 1)*4128;
        float4 eA = *(const float4*)(efb + ksv*516 + pi2*8);
        float4 eB = *(const float4*)(efb + ksv*516 + pi2*8 + 4);
        float4 eC = *(const float4*)(efb + ksv*516 + (pi2+32)*8);
        float4 eD = *(const float4*)(efb + ksv*516 + (pi2+32)*8 + 4);
        float pvl[8], pvh[8];
        pvl[0] = eA.x*rinv_lo; pvl[1] = eA.y*rinv_lo;
        pvl[2] = eA.z*rinv_lo; pvl[3] = eA.w*rinv_lo;
        pvl[4] = eB.x*rinv_lo; pvl[5] = eB.y*rinv_lo;
        pvl[6] = eB.z*rinv_lo; pvl[7] = eB.w*rinv_lo;
        pvh[0] = eC.x*rinv_hi; pvh[1] = eC.y*rinv_hi;
        pvh[2] = eC.z*rinv_hi; pvh[3] = eC.w*rinv_hi;
        pvh[4] = eD.x*rinv_hi; pvh[5] = eD.y*rinv_hi;
        pvh[6] = eD.z*rinv_hi; pvh[7] = eD.w*rinv_hi;

        *(float4*)(arow_lo + m0 + pj0)     = make_float4(pvl[0], pvl[1], pvl[2], pvl[3]);
        *(float4*)(arow_lo + m0 + pj0 + 4) = make_float4(pvl[4], pvl[5], pvl[6], pvl[7]);
        *(float4*)(arow_hi + m0 + pj0)     = make_float4(pvh[0], pvh[1], pvh[2], pvh[3]);
        *(float4*)(arow_hi + m0 + pj0 + 4) = make_float4(pvh[4], pvh[5], pvh[6], pvh[7]);

        #pragma unroll
        for (int j = 0; j < 4; j++) {
            int ls = lsb_lo + j;
            int s = (nbp_lo + (ls >> 1) + ksv) & 3;
            uint2 u2;
            u2.x = f2tf32(pvl[j]);
            u2.y = f2tf32(pvl[j + 4]);
            *(uint2*)(bf + ksv*512 + ls*16 + s*4 + nblo_lo*2) = u2;
        }
        #pragma unroll
        for (int j = 0; j < 4; j++) {
            int ls = lsb_hi + j;
            int s = (nbp_hi + (ls >> 1) + ksv) & 3;
            uint2 u2;
            u2.x = f2tf32(pvh[j]);
            u2.y = f2tf32(pvh[j + 4]);
            *(uint2*)(bf + ksv*512 + ls*16 + s*4 + nblo_hi*2) = u2;
        }
        __syncthreads();                      // bf ready

        // ---- phase B: cacc += V . P^T via mma.sync tf32 ----
        const uint4* vsp = (const uint4*)(smf + 12352 + (tt & 1)*8192) + w*8*32 + lane;
        #pragma unroll
        for (int kv = 0; kv < 8; kv++) {
            uint4 a = vsp[kv*32];
            unsigned ar[4] = {a.x, a.y, a.z, a.w};
            #pragma unroll
            for (int np2 = 0; np2 < 4; np2++) {
                int s = (np2 + (lane >> 1) + kv) & 3;
                uint4 bv = *(const uint4*)(bf + kv*512 + lane*16 + s*4);
                mma_tf32(cacc[2*np2],     ar, bv.x, bv.y);
                mma_tf32(cacc[2*np2 + 1], ar, bv.z, bv.w);
            }
        }
    }

    // ---- epilogue: atomic out accumulation ----
    float gm = gamma[0];
    int rowc = lane >> 2, colb = (lane & 3) << 1;
    #pragma unroll
    for (int nb = 0; nb < 8; nb++) {
        int i = nb*8 + colb;
        size_t a0 = ((size_t)b*CC + w*16 + rowc)*NN + n0 + i;
        atomicAdd(outp + a0,            gm*cacc[nb][0]);
        atomicAdd(outp + a0 + 1,        gm*cacc[nb][1]);
        atomicAdd(outp + a0 + 8*NN,     gm*cacc[nb][2]);
        atomicAdd(outp + a0 + 8*NN + 1, gm*cacc[nb][3]);
    }
}

// ================= launch =================
extern "C" void kernel_launch(void* const* d_in, const int* in_sizes, int n_in,
                              void* d_out, int out_size)
{
    const float* x     = (const float*)d_in[0];
    const float* wq    = (const float*)d_in[1];
    const float* bq    = (const float*)d_in[2];
    const float* wk    = (const float*)d_in[3];
    const float* bk    = (const float*)d_in[4];
    const float* wv    = (const float*)d_in[5];
    const float* bv    = (const float*)d_in[6];
    const float* gamma = (const float*)d_in[7];

    float* outp  = (float*)d_out;
    float* attnp = outp + (size_t)BB*CC*NN;

    const int SM1 = (160*132 + 160 + 2*4096) * 4;      // 117,888 B
    const int SM3 = 28736 * 4;                         // 114,944 B
    cudaFuncSetAttribute(qkv_kernel,  cudaFuncAttributeMaxDynamicSharedMemorySize, SM1);
    cudaFuncSetAttribute(attn_kernel, cudaFuncAttributeMaxDynamicSharedMemorySize, SM3);

    qkv_kernel<<<BB*(NN/64), 256, SM1>>>(x, wq, bq, wk, bk, wv, bv, outp);
    expwrite_kernel<<<NCOMP + NVF, 256>>>(attnp);
    attn_kernel<<<NCOMP + NZERO, 256, SM3>>>(gamma, outp, attnp);
}